// round 7
// baseline (speedup 1.0000x reference)
#include <cuda_runtime.h>

// FWHT, 4096 rows x 16384 fp32. Persistent CTAs (grid=148, 1/SM), 1024 thr,
// register prefetch of next row + DOUBLE-BUFFERED smem (2 barriers/row).
// Per-row dataflow:
//   P1: regs H16 over bits {13,12,1,0}  (float4 LDG; vector lanes = bits 1,0)
//   X1 (buf p) -> P2: regs H16 over bits {11..8}  (same-address writeback)
//   X2 (buf p) -> P3: regs H16 over bits {7..4}
//   shfl stages over bits {3,2}; scale; coalesced STG.
//   Next row's P1 writes buf p^1 -> no WAR barrier needed.
// Swizzle phys(i) = i + 16*(i>>8): injective, 16B-aligned, conflict-free for
// all four smem patterns (X2-read half-warps hit complementary bank halves).

#define N_ELEM 16384
#define THREADS 1024
#define BUF_FLOATS 17408   // max phys index 16383 + 16*63 = 17391
#define GRID 148

__device__ __forceinline__ int physz(int i) { return i + ((i >> 8) << 4); }

template <int N>
__device__ __forceinline__ void hadN(float* v) {
#pragma unroll
    for (int s = 1; s < N; s <<= 1) {
#pragma unroll
        for (int i = 0; i < N; i++) {
            if ((i & s) == 0) {
                float a = v[i];
                float b = v[i | s];
                v[i]     = a + b;
                v[i | s] = a - b;
            }
        }
    }
}

__global__ __launch_bounds__(THREADS, 1)
void fwht_kernel(const float* __restrict__ in, float* __restrict__ out,
                 int nrows) {
    extern __shared__ float sh[];
    const int t = threadIdx.x;
    const int l = t & 31;

    // Immediate-foldable bases:
    // P1: phys(j<<12 | t<<2)                 = pa  + j*4352
    // P2: phys((t>>8)<<12 | r<<8 | (t&255))  = pb1 + r*272
    // P3: phys((t>>4)<<8  | r<<4 | (t&15))   = pb2 + r*16
    const int pa  = (t << 2) + ((t >> 6) << 4);
    const int b1  = ((t >> 8) << 12) | (t & 255);
    const int pb1 = physz(b1);
    const int b2  = ((t >> 4) << 8) | (t & 15);
    const int pb2 = physz(b2);

    const float s3 = (l & 8) ? -1.0f : 1.0f;
    const float s2 = (l & 4) ? -1.0f : 1.0f;

    float v[16];

    int row = blockIdx.x;
    {
        const float4* __restrict__ p4 =
            reinterpret_cast<const float4*>(in + (size_t)row * N_ELEM + (t << 2));
#pragma unroll
        for (int j = 0; j < 4; j++) {
            float4 f = p4[(size_t)j << 10];
            v[4 * j + 0] = f.x; v[4 * j + 1] = f.y;
            v[4 * j + 2] = f.z; v[4 * j + 3] = f.w;
        }
    }

    int p = 0;  // buffer parity
    while (row < nrows) {
        const int nextrow = row + GRID;
        float* __restrict__ buf = sh + p * BUF_FLOATS;

        // ---- prefetch next row into vn (in flight during P1..P3)
        float vn[16];
        if (nextrow < nrows) {
            const float4* __restrict__ p4 =
                reinterpret_cast<const float4*>(in + (size_t)nextrow * N_ELEM + (t << 2));
#pragma unroll
            for (int j = 0; j < 4; j++) {
                float4 f = p4[(size_t)j << 10];
                vn[4 * j + 0] = f.x; vn[4 * j + 1] = f.y;
                vn[4 * j + 2] = f.z; vn[4 * j + 3] = f.w;
            }
        }

        // ---- P1: butterflies bits {13,12,1,0}; STS.128 into buf[p]
        hadN<16>(v);
#pragma unroll
        for (int j = 0; j < 4; j++) {
            *reinterpret_cast<float4*>(&buf[pa + j * 4352]) =
                make_float4(v[4 * j + 0], v[4 * j + 1], v[4 * j + 2], v[4 * j + 3]);
        }
        __syncthreads();  // B1: buf[p] fully written

        // ---- P2: bits {11..8}; in-place (same-address) writeback
#pragma unroll
        for (int r = 0; r < 16; r++) v[r] = buf[pb1 + r * 272];
        hadN<16>(v);
#pragma unroll
        for (int r = 0; r < 16; r++) buf[pb1 + r * 272] = v[r];
        __syncthreads();  // B2: buf[p] fully rewritten

        // ---- P3: bits {7..4}; no trailing barrier (next P1 uses buf[p^1])
#pragma unroll
        for (int r = 0; r < 16; r++) v[r] = buf[pb2 + r * 16];
        hadN<16>(v);

        // ---- bits {3,2} on lane bits 3,2 via shfl-xor sign trick
#pragma unroll
        for (int r = 0; r < 16; r++) {
            float q = __shfl_xor_sync(0xffffffffu, v[r], 8);
            v[r] = fmaf(s3, v[r], q);
        }
#pragma unroll
        for (int r = 0; r < 16; r++) {
            float q = __shfl_xor_sync(0xffffffffu, v[r], 4);
            v[r] = fmaf(s2, v[r], q);
        }

        // ---- scale 2^-7, coalesced store (full 64B sectors)
        float* __restrict__ pout = out + (size_t)row * N_ELEM;
#pragma unroll
        for (int r = 0; r < 16; r++)
            pout[b2 + (r << 4)] = v[r] * 0.0078125f;

        // ---- rotate pipeline
        row = nextrow;
        p ^= 1;
#pragma unroll
        for (int k = 0; k < 16; k++) v[k] = vn[k];
    }
}

extern "C" void kernel_launch(void* const* d_in, const int* in_sizes, int n_in,
                              void* d_out, int out_size) {
    const float* phi = (const float*)d_in[0];
    float* out = (float*)d_out;

    const size_t smem = 2 * BUF_FLOATS * sizeof(float);  // 139264 B
    cudaFuncSetAttribute(fwht_kernel,
                         cudaFuncAttributeMaxDynamicSharedMemorySize,
                         (int)smem);

    const int nrows = in_sizes[0] / N_ELEM;  // 4096
    const int grid = nrows < GRID ? nrows : GRID;
    fwht_kernel<<<grid, THREADS, smem>>>(phi, out, nrows);
}